// round 15
// baseline (speedup 1.0000x reference)
#include <cuda_runtime.h>
#include <cuda_fp16.h>
#include <math.h>
#include <stdint.h>

// Problem constants
#define Bb   32
#define Ss   512
#define Dd   512
#define Hh   8
#define Ee   8
#define FFNf 2048
#define Tt   (Bb*Ss)     // 16384 tokens

// ===========================================================================
// Scratch (device globals)
// ===========================================================================
__device__ float g_h1[Tt*Dd];
__device__ float g_router[Tt*Ee];
__device__ int   g_cnt[Ee];
__device__ int   g_tok[Ee*Tt];
__device__ float g_wt[Ee*Tt];
__device__ float g_rsum[Ee];
__device__ float g_rsin[Ss*16];
__device__ float g_rcos[Ss*16];

// fp16 buffers
__device__ __half g_hsh  [Tt*Dd];
__device__ __half g_atth [Tt*Dd];
__device__ __half g_projh[Tt*Dd];
__device__ __half g_h1h  [Tt*Dd];
__device__ __half g_qh   [Tt*Dd];          // head-major [b][h][s][64]
__device__ __half g_kh   [Tt*Dd];
__device__ __half g_vh   [Tt*Dd];
__device__ __half g_wqkvh[3*Dd*Dd];        // q|k|v rows concatenated [1536][512]
__device__ __half g_woh  [Dd*Dd];
__device__ __half g_w1h  [(size_t)Ee*FFNf*Dd];
__device__ __half g_w2h  [(size_t)Ee*Dd*FFNf];
__device__ __half g_hbufh[(size_t)Tt*2*FFNf];
__device__ __half g_moe2h[(size_t)Tt*2*Dd];

// ===========================================================================
// One fused setup kernel
// ===========================================================================
#define C_HS (Tt*Dd/4)
#define C_W  (Dd*Dd/4)
#define C_W1 (Ee*FFNf*Dd/4)
#define C_W2 (Ee*Dd*FFNf/4)
#define CONV_TOT (C_HS + 4*C_W + C_W1 + C_W2)
#define CONV_THREADS (CONV_TOT + Ss*16 + Ee)

__global__ void conv_all(const float* __restrict__ hs,
                         const float* __restrict__ qw, const float* __restrict__ kw,
                         const float* __restrict__ vw, const float* __restrict__ ow,
                         const float* __restrict__ w1, const float* __restrict__ w2) {
    int i = blockIdx.x * 256 + threadIdx.x;
    const int o1 = C_HS, o2 = o1 + C_W, o3 = o2 + C_W, o4 = o3 + C_W,
              o5 = o4 + C_W, o6 = o5 + C_W1, o7 = o6 + C_W2;
    if (i < o7) {
        const float* s; __half* d; int l;
        if (i < o1)      { s = hs; d = g_hsh;              l = i; }
        else if (i < o2) { s = qw; d = g_wqkvh;            l = i - o1; }
        else if (i < o3) { s = kw; d = g_wqkvh + Dd*Dd;    l = i - o2; }
        else if (i < o4) { s = vw; d = g_wqkvh + 2*Dd*Dd;  l = i - o3; }
        else if (i < o5) { s = ow; d = g_woh;              l = i - o4; }
        else if (i < o6) { s = w1; d = g_w1h;              l = i - o5; }
        else             { s = w2; d = g_w2h;              l = i - o6; }
        float4 v = ((const float4*)s)[l];
        ((__half2*)d)[2*l]     = __floats2half2_rn(v.x, v.y);
        ((__half2*)d)[2*l + 1] = __floats2half2_rn(v.z, v.w);
    } else if (i < o7 + Ss*16) {
        int idx = i - o7;
        int s = idx >> 4, ii = idx & 15;
        float inv = powf(10000.0f, -(float)ii / 16.0f);
        float ang = (float)s * inv;
        g_rsin[idx] = sinf(ang);
        g_rcos[idx] = cosf(ang);
    } else if (i < o7 + Ss*16 + Ee) {
        g_cnt[i - o7 - Ss*16] = 0;
    }
}

// ===========================================================================
// HMMA helpers
// ===========================================================================
__device__ __forceinline__ uint32_t smem_to_u32(const void* p) {
    uint32_t a;
    asm("{ .reg .u64 t; cvta.to.shared.u64 t, %1; cvt.u32.u64 %0, t; }" : "=r"(a) : "l"(p));
    return a;
}
__device__ __forceinline__ void ldsm_x4(uint32_t& r0, uint32_t& r1, uint32_t& r2, uint32_t& r3, uint32_t a) {
    asm volatile("ldmatrix.sync.aligned.m8n8.x4.shared.b16 {%0,%1,%2,%3}, [%4];"
        : "=r"(r0), "=r"(r1), "=r"(r2), "=r"(r3) : "r"(a));
}
__device__ __forceinline__ void ldsm_x2(uint32_t& r0, uint32_t& r1, uint32_t a) {
    asm volatile("ldmatrix.sync.aligned.m8n8.x2.shared.b16 {%0,%1}, [%2];"
        : "=r"(r0), "=r"(r1) : "r"(a));
}
__device__ __forceinline__ void ldsm_x2_trans(uint32_t& r0, uint32_t& r1, uint32_t a) {
    asm volatile("ldmatrix.sync.aligned.m8n8.x2.trans.shared.b16 {%0,%1}, [%2];"
        : "=r"(r0), "=r"(r1) : "r"(a));
}
__device__ __forceinline__ void mma16816(float* c, uint32_t a0, uint32_t a1, uint32_t a2, uint32_t a3,
                                         uint32_t b0, uint32_t b1) {
    asm volatile("mma.sync.aligned.m16n8k16.row.col.f32.f16.f16.f32 "
        "{%0,%1,%2,%3}, {%4,%5,%6,%7}, {%8,%9}, {%0,%1,%2,%3};"
        : "+f"(c[0]), "+f"(c[1]), "+f"(c[2]), "+f"(c[3])
        : "r"(a0), "r"(a1), "r"(a2), "r"(a3), "r"(b0), "r"(b1));
}
#define CP_ASYNC16(dst, src) \
    asm volatile("cp.async.cg.shared.global [%0], [%1], 16;" :: "r"(dst), "l"(src))
#define CP_COMMIT() asm volatile("cp.async.commit_group;" ::: "memory")
#define CP_WAIT0()  asm volatile("cp.async.wait_group 0;" ::: "memory")
#define CP_WAIT1()  asm volatile("cp.async.wait_group 1;" ::: "memory")

__device__ __forceinline__ uint32_t f2h2(float x, float y) {
    __half2 p = __floats2half2_rn(x, y);
    return *(uint32_t*)&p;
}

// ===========================================================================
// fp16 HMMA GEMM, 3-stage cp.async ring (no trailing barrier).
// MODE 0: 128x128 tile, warp 64x32, 2 CTA/SM  (rope-fused epilogue needs 32-col warps)
// MODE 1/2/3: 128x64 tile, warp 64x16, __launch_bounds__(256,3) -> 3 CTA/SM
// ===========================================================================
template<int MODE>
__global__ void __launch_bounds__(256, (MODE == 0) ? 2 : 3)
hgemm(const __half* __restrict__ A,
      const __half* __restrict__ Bw,
      const float* __restrict__ bp0,
      const float* __restrict__ bp1,
      const float* __restrict__ bp2) {
    constexpr int K   = (MODE == 2) ? FFNf : Dd;
    constexpr int NC  = K / 64;
    constexpr int NW  = (MODE == 0) ? 3*Dd : (MODE == 1) ? FFNf : Dd;
    constexpr bool GATH = (MODE == 1) || (MODE == 2);
    constexpr int BN  = (MODE == 0) ? 128 : 64;      // CTA n-tile
    constexpr int WN  = BN / 4;                      // warp n-tile (32 or 16)
    constexpr int NT_ = WN / 8;                      // 4 or 2
    constexpr int ASZ = 16384;                       // 128 rows x 128B
    constexpr int BSZ = BN * 128;
    constexpr int STG = ASZ + BSZ;

    extern __shared__ char smem[];
    uint32_t sb = smem_to_u32(smem);
    int tid = threadIdx.x, wid = tid >> 5, lane = tid & 31;

    int e   = GATH ? blockIdx.z : 0;
    int cnt = GATH ? g_cnt[e] : Tt;
    int m0  = blockIdx.x * 128;
    if (m0 >= cnt) return;
    int n0  = blockIdx.y * BN;

    const __half* Wp = Bw + (size_t)e * NW * K;
    const float*  bp = bp0 + (size_t)e * NW;

    int*   s_row  = (int*)(smem);
    int*   s_slot = (int*)(smem + 512);
    float* s_wt   = (float*)(smem + 1024);
    if (tid < 128) {
        int r = m0 + tid;
        if (!GATH) { s_row[tid] = r; s_slot[tid] = r; }
        else {
            if (r < cnt) {
                int sl = g_tok[e * Tt + r];
                s_slot[tid] = sl;
                s_row[tid]  = (MODE == 1) ? (sl >> 1) : sl;
                if (MODE == 2) s_wt[tid] = g_wt[e * Tt + r];
            } else { s_slot[tid] = -1; s_row[tid] = 0; if (MODE == 2) s_wt[tid] = 0.f; }
        }
    }
    __syncthreads();

    auto LOAD = [&](int c, int b) {
        int cbase = c * 64;
        uint32_t dstA = sb + 2048 + b * STG;
        uint32_t dstB = dstA + ASZ;
#pragma unroll
        for (int i = 0; i < 4; i++) {
            int u = tid + i * 256;
            int r = u >> 3, c16 = u & 7;
            uint32_t off = (uint32_t)(r * 128 + ((c16 * 16) ^ ((r & 7) << 4)));
            CP_ASYNC16(dstA + off, A + (size_t)s_row[r] * K + cbase + c16 * 8);
        }
#pragma unroll
        for (int i = 0; i < BN / 32; i++) {
            int u = tid + i * 256;
            int r = u >> 3, c16 = u & 7;
            uint32_t off = (uint32_t)(r * 128 + ((c16 * 16) ^ ((r & 7) << 4)));
            CP_ASYNC16(dstB + off, Wp + (size_t)(n0 + r) * K + cbase + c16 * 8);
        }
        CP_COMMIT();
    };

    LOAD(0, 0);
    if (NC > 1) LOAD(1, 1);

    float acc[4][NT_][4];
#pragma unroll
    for (int a = 0; a < 4; a++)
#pragma unroll
        for (int b = 0; b < NT_; b++)
#pragma unroll
            for (int c = 0; c < 4; c++) acc[a][b][c] = 0.f;

    int wm = (wid & 1) * 64, wn = (wid >> 1) * WN;
    uint32_t swz = (uint32_t)((lane & 7) << 4);
    int arow = wm + (lane & 7) + ((lane >> 3) & 1) * 8;
    uint32_t acolsel = ((lane >> 4) & 1) * 16;
    int brow = wn + (lane & 7);
    uint32_t bcolsel = ((lane >> 3) & 1) * 16;

    for (int c = 0; c < NC; c++) {
        if (c + 2 < NC) { CP_WAIT1(); } else { CP_WAIT0(); }
        __syncthreads();
        int buf = c % 3;
        uint32_t sA = sb + 2048 + buf * STG;
        uint32_t sB = sA + ASZ;
#pragma unroll
        for (int kk = 0; kk < 4; kk++) {
            uint32_t kb = (uint32_t)(kk * 32);
            uint32_t b0[NT_], b1[NT_];
#pragma unroll
            for (int nt = 0; nt < NT_; nt++)
                ldsm_x2(b0[nt], b1[nt], sB + (brow + nt * 8) * 128 + ((kb + bcolsel) ^ swz));
#pragma unroll
            for (int mt = 0; mt < 4; mt++) {
                uint32_t a0, a1, a2, a3;
                ldsm_x4(a0, a1, a2, a3, sA + (arow + mt * 16) * 128 + ((kb + acolsel) ^ swz));
#pragma unroll
                for (int nt = 0; nt < NT_; nt++)
                    mma16816(acc[mt][nt], a0, a1, a2, a3, b0[nt], b1[nt]);
            }
        }
        // no trailing barrier: 3-buffer ring keeps LOAD(c+2) disjoint
        if (c + 2 < NC) LOAD(c + 2, (c + 2) % 3);
    }

    // ---- epilogue from registers ----
    int t4 = lane >> 2, tq = lane & 3;
#pragma unroll
    for (int mt = 0; mt < 4; mt++) {
#pragma unroll
        for (int rr = 0; rr < 2; rr++) {
            int rl = wm + mt * 16 + t4 + rr * 8;
            int slot = s_slot[rl];
            if (slot < 0) continue;
            if (MODE == 0) {
                int b = slot >> 9, spos = slot & 511;
                int ncb = n0 + wn;
                int which = ncb >> 9;
                int colb = ncb & 511;
                int h = colb >> 6;
                int hd0 = colb & 63;
                const float* bb = (which == 0) ? bp0 : (which == 1) ? bp1 : bp2;
                __half* dstb = ((which == 0) ? g_qh : (which == 1) ? g_kh : g_vh)
                               + ((size_t)(b * Hh + h) * Ss + spos) * 64;
                float vx[NT_], vy[NT_];
#pragma unroll
                for (int nt = 0; nt < NT_; nt++) {
                    int col = colb + nt * 8 + tq * 2;
                    vx[nt] = acc[mt][nt][rr * 2 + 0] + bb[col];
                    vy[nt] = acc[mt][nt][rr * 2 + 1] + bb[col + 1];
                }
                if (which < 2 && hd0 == 0) {
#pragma unroll
                    for (int nt = 0; nt < 2; nt++) {
                        int i = nt * 8 + tq * 2;
                        float sn0 = g_rsin[spos * 16 + i],     cs0 = g_rcos[spos * 16 + i];
                        float sn1 = g_rsin[spos * 16 + i + 1], cs1 = g_rcos[spos * 16 + i + 1];
                        float x1 = vx[nt], x2 = vx[nt + 2];
                        vx[nt]     = x1 * cs0 - x2 * sn0;
                        vx[nt + 2] = x2 * cs0 + x1 * sn0;
                        float y1 = vy[nt], y2 = vy[nt + 2];
                        vy[nt]     = y1 * cs1 - y2 * sn1;
                        vy[nt + 2] = y2 * cs1 + y1 * sn1;
                    }
                }
                float qs = (which == 0) ? 0.125f : 1.0f;
#pragma unroll
                for (int nt = 0; nt < NT_; nt++) {
                    int d = hd0 + nt * 8 + tq * 2;
                    *(__half2*)(dstb + d) = __floats2half2_rn(vx[nt] * qs, vy[nt] * qs);
                }
            } else {
#pragma unroll
                for (int nt = 0; nt < NT_; nt++) {
                    int gc = n0 + wn + nt * 8 + tq * 2;
                    float c0 = acc[mt][nt][rr * 2 + 0];
                    float c1 = acc[mt][nt][rr * 2 + 1];
                    if (MODE == 3) {
                        *(__half2*)(g_projh + (size_t)slot * Dd + gc) =
                            __floats2half2_rn(c0 + bp0[gc], c1 + bp0[gc + 1]);
                    } else if (MODE == 1) {
                        float x0 = c0 + bp[gc], x1 = c1 + bp[gc + 1];
                        float g0 = 0.5f * x0 * (1.0f + erff(x0 * 0.70710678f));
                        float g1 = 0.5f * x1 * (1.0f + erff(x1 * 0.70710678f));
                        *(__half2*)(g_hbufh + (size_t)slot * FFNf + gc) = __floats2half2_rn(g0, g1);
                    } else {
                        float wt = s_wt[rl];
                        *(__half2*)(g_moe2h + (size_t)slot * Dd + gc) =
                            __floats2half2_rn(wt * (c0 + bp[gc]), wt * (c1 + bp[gc + 1]));
                    }
                }
            }
        }
    }
}

#define SMEM_B0 (2048 + 3*(16384 + 16384))
#define SMEM_BS (2048 + 3*(16384 + 8192))

// ===========================================================================
// HMMA flash attention (round-8 form)
// ===========================================================================
__global__ void __launch_bounds__(128) fattn() {
    __shared__ __align__(16) __half Qs[64*64];
    __shared__ __align__(16) __half Ks[2][64*64];
    __shared__ __align__(16) __half Vs[2][64*64];

    int qt = blockIdx.x;
    int bh = blockIdx.y;
    int tid = threadIdx.x, wid = tid >> 5, lane = tid & 31;

    const __half* Qg = g_qh + ((size_t)bh * Ss + qt * 64) * 64;
    const __half* Kg = g_kh + (size_t)bh * Ss * 64;
    const __half* Vg = g_vh + (size_t)bh * Ss * 64;

    uint32_t sq  = smem_to_u32(Qs);
    uint32_t sk0 = smem_to_u32(Ks);
    uint32_t sv0 = smem_to_u32(Vs);

#pragma unroll
    for (int i = 0; i < 4; i++) {
        int u = tid + i * 128;
        int r = u >> 3, c16 = u & 7;
        uint32_t off = (uint32_t)(r * 128 + ((c16 * 16) ^ ((r & 7) << 4)));
        CP_ASYNC16(sq + off, Qg + r * 64 + c16 * 8);
    }
    CP_COMMIT();

    auto LOADKV = [&](int j, int b) {
        const __half* kg = Kg + j * 64 * 64;
        const __half* vg = Vg + j * 64 * 64;
        uint32_t dk = sk0 + b * 8192, dv = sv0 + b * 8192;
#pragma unroll
        for (int i = 0; i < 4; i++) {
            int u = tid + i * 128;
            int r = u >> 3, c16 = u & 7;
            uint32_t off = (uint32_t)(r * 128 + ((c16 * 16) ^ ((r & 7) << 4)));
            CP_ASYNC16(dk + off, kg + r * 64 + c16 * 8);
            CP_ASYNC16(dv + off, vg + r * 64 + c16 * 8);
        }
        CP_COMMIT();
    };
    LOADKV(0, 0);
    CP_WAIT0();
    __syncthreads();

    int wm = wid * 16;
    uint32_t swz = (uint32_t)((lane & 7) << 4);
    int arow = wm + (lane & 7) + ((lane >> 3) & 1) * 8;
    uint32_t acolsel = ((lane >> 4) & 1) * 16;
    uint32_t qa[4][4];
#pragma unroll
    for (int kk = 0; kk < 4; kk++)
        ldsm_x4(qa[kk][0], qa[kk][1], qa[kk][2], qa[kk][3],
                sq + arow * 128 + ((kk * 32 + acolsel) ^ swz));

    float o_acc[8][4];
#pragma unroll
    for (int a = 0; a < 8; a++)
#pragma unroll
        for (int b = 0; b < 4; b++) o_acc[a][b] = 0.f;
    float m0 = -1e30f, m1 = -1e30f, l0 = 0.f, l1 = 0.f;

    int brow = lane & 7;
    uint32_t bcolsel = ((lane >> 3) & 1) * 16;
    int vrow_l = lane & 15;

    for (int j = 0; j < 8; j++) {
        if (j + 1 < 8) LOADKV(j + 1, (j + 1) & 1);
        uint32_t sk = sk0 + (j & 1) * 8192;
        uint32_t sv = sv0 + (j & 1) * 8192;

        float s[8][4];
#pragma unroll
        for (int a = 0; a < 8; a++)
#pragma unroll
            for (int b = 0; b < 4; b++) s[a][b] = 0.f;
#pragma unroll
        for (int kk = 0; kk < 4; kk++) {
            uint32_t kb = (uint32_t)(kk * 32);
#pragma unroll
            for (int nt = 0; nt < 8; nt++) {
                uint32_t b0, b1;
                ldsm_x2(b0, b1, sk + (nt * 8 + brow) * 128 + ((kb + bcolsel) ^ swz));
                mma16816(s[nt], qa[kk][0], qa[kk][1], qa[kk][2], qa[kk][3], b0, b1);
            }
        }

        float tm0 = -1e30f, tm1 = -1e30f;
#pragma unroll
        for (int nt = 0; nt < 8; nt++) {
            tm0 = fmaxf(tm0, fmaxf(s[nt][0], s[nt][1]));
            tm1 = fmaxf(tm1, fmaxf(s[nt][2], s[nt][3]));
        }
        tm0 = fmaxf(tm0, __shfl_xor_sync(0xffffffffu, tm0, 1));
        tm0 = fmaxf(tm0, __shfl_xor_sync(0xffffffffu, tm0, 2));
        tm1 = fmaxf(tm1, __shfl_xor_sync(0xffffffffu, tm1, 1));
        tm1 = fmaxf(tm1, __shfl_xor_sync(0xffffffffu, tm1, 2));
        float nm0 = fmaxf(m0, tm0), nm1 = fmaxf(m1, tm1);
        float sc0 = __expf(m0 - nm0), sc1 = __expf(m1 - nm1);
        m0 = nm0; m1 = nm1;
        l0 *= sc0; l1 *= sc1;
#pragma unroll
        for (int nt = 0; nt < 8; nt++) {
            o_acc[nt][0] *= sc0; o_acc[nt][1] *= sc0;
            o_acc[nt][2] *= sc1; o_acc[nt][3] *= sc1;
        }
        float sum0 = 0.f, sum1 = 0.f;
#pragma unroll
        for (int nt = 0; nt < 8; nt++) {
            s[nt][0] = __expf(s[nt][0] - m0); s[nt][1] = __expf(s[nt][1] - m0);
            s[nt][2] = __expf(s[nt][2] - m1); s[nt][3] = __expf(s[nt][3] - m1);
            sum0 += s[nt][0] + s[nt][1];
            sum1 += s[nt][2] + s[nt][3];
        }
        sum0 += __shfl_xor_sync(0xffffffffu, sum0, 1);
        sum0 += __shfl_xor_sync(0xffffffffu, sum0, 2);
        sum1 += __shfl_xor_sync(0xffffffffu, sum1, 1);
        sum1 += __shfl_xor_sync(0xffffffffu, sum1, 2);
        l0 += sum0; l1 += sum1;

#pragma unroll
        for (int c = 0; c < 4; c++) {
            uint32_t a0 = f2h2(s[2*c][0],   s[2*c][1]);
            uint32_t a1 = f2h2(s[2*c][2],   s[2*c][3]);
            uint32_t a2 = f2h2(s[2*c+1][0], s[2*c+1][1]);
            uint32_t a3 = f2h2(s[2*c+1][2], s[2*c+1][3]);
            uint32_t vbase = sv + (16 * c + vrow_l) * 128;
#pragma unroll
            for (int nt = 0; nt < 8; nt++) {
                uint32_t b0, b1;
                ldsm_x2_trans(b0, b1, vbase + ((nt * 16) ^ swz));
                mma16816(o_acc[nt], a0, a1, a2, a3, b0, b1);
            }
        }

        CP_WAIT0();
        __syncthreads();
    }

    float inv0 = 1.0f / l0, inv1 = 1.0f / l1;
    int h = bh & 7, b = bh >> 3;
    int r0 = qt * 64 + wm + (lane >> 2);
    int t0 = b * Ss + r0;
#pragma unroll
    for (int nt = 0; nt < 8; nt++) {
        int col = h * 64 + nt * 8 + (lane & 3) * 2;
        *(__half2*)(g_atth + (size_t)t0 * Dd + col) =
            __floats2half2_rn(o_acc[nt][0] * inv0, o_acc[nt][1] * inv0);
        *(__half2*)(g_atth + (size_t)(t0 + 8) * Dd + col) =
            __floats2half2_rn(o_acc[nt][2] * inv1, o_acc[nt][3] * inv1);
    }
}

// ===========================================================================
// Residual + LayerNorm; mode 0 also emits fp16 h1.
// ===========================================================================
__global__ void add_ln(const float* __restrict__ xe,
                       const float* __restrict__ g, const float* __restrict__ bb,
                       float* __restrict__ oe, int mode) {
    int row = blockIdx.x, tid = threadIdx.x;
    size_t base = (size_t)row * Dd;
    float v[4]; float s = 0.0f, sq = 0.0f;
#pragma unroll
    for (int i = 0; i < 4; i++) {
        int c = tid + i * 128;
        float t;
        if (mode == 0) t = xe[base + c] + __half2float(g_projh[base + c]);
        else           t = g_h1[base + c]
                         + (__half2float(g_moe2h[(size_t)(2*row) * Dd + c])
                          + __half2float(g_moe2h[(size_t)(2*row+1) * Dd + c]));
        v[i] = t; s += t; sq += t * t;
    }
#pragma unroll
    for (int off = 16; off; off >>= 1) {
        s  += __shfl_down_sync(0xffffffffu, s,  off);
        sq += __shfl_down_sync(0xffffffffu, sq, off);
    }
    __shared__ float rs[4], rq[4];
    int warp = tid >> 5, lane = tid & 31;
    if (lane == 0) { rs[warp] = s; rq[warp] = sq; }
    __syncthreads();
    if (tid == 0) {
        float S = rs[0] + rs[1] + rs[2] + rs[3];
        float Q = rq[0] + rq[1] + rq[2] + rq[3];
        rs[0] = S; rq[0] = Q;
    }
    __syncthreads();
    float mean = rs[0] * (1.0f / Dd);
    float var  = rq[0] * (1.0f / Dd) - mean * mean;
    float rstd = rsqrtf(var + 1e-5f);
    float* o = (mode == 0) ? g_h1 : oe;
#pragma unroll
    for (int i = 0; i < 4; i++) {
        int c = tid + i * 128;
        float r = (v[i] - mean) * rstd * g[c] + bb[c];
        o[base + c] = r;
        if (mode == 0) g_h1h[base + c] = __float2half(r);
    }
}

// ===========================================================================
// Router + lb loss
// ===========================================================================
__global__ void router_kernel(const float* __restrict__ gw) {
    int warp = threadIdx.x >> 5, lane = threadIdx.x & 31;
    int t = blockIdx.x * 4 + warp;
    const float* x = g_h1 + (size_t)t * Dd;
    float acc[8] = {};
    for (int d = lane; d < Dd; d += 32) {
        float xv = x[d];
#pragma unroll
        for (int e = 0; e < 8; e++) acc[e] += xv * gw[e * Dd + d];
    }
#pragma unroll
    for (int e = 0; e < 8; e++)
#pragma unroll
        for (int off = 16; off; off >>= 1)
            acc[e] += __shfl_xor_sync(0xffffffffu, acc[e], off);

    if (lane == 0) {
        float mx = acc[0];
#pragma unroll
        for (int e = 1; e < 8; e++) mx = fmaxf(mx, acc[e]);
        float p[8], sm = 0.0f;
#pragma unroll
        for (int e = 0; e < 8; e++) { p[e] = __expf(acc[e] - mx); sm += p[e]; }
        float inv = 1.0f / sm;
#pragma unroll
        for (int e = 0; e < 8; e++) { p[e] *= inv; g_router[t * 8 + e] = p[e]; }
        int i1 = 0;
#pragma unroll
        for (int e = 1; e < 8; e++) if (p[e] > p[i1]) i1 = e;
        int i2 = (i1 == 0) ? 1 : 0;
#pragma unroll
        for (int e = 0; e < 8; e++) if (e != i1 && p[e] > p[i2]) i2 = e;
        float wsum = p[i1] + p[i2];
        int s1 = atomicAdd(&g_cnt[i1], 1);
        g_tok[i1 * Tt + s1] = t * 2;     g_wt[i1 * Tt + s1] = p[i1] / wsum;
        int s2 = atomicAdd(&g_cnt[i2], 1);
        g_tok[i2 * Tt + s2] = t * 2 + 1; g_wt[i2 * Tt + s2] = p[i2] / wsum;
    }
}

__global__ void lb1_kernel() {
    int e = blockIdx.x;
    float p = 0.0f;
    for (int t = threadIdx.x; t < Tt; t += 256) p += g_router[t * 8 + e];
    __shared__ float sm[256];
    sm[threadIdx.x] = p; __syncthreads();
    for (int s = 128; s; s >>= 1) {
        if (threadIdx.x < s) sm[threadIdx.x] += sm[threadIdx.x + s];
        __syncthreads();
    }
    if (threadIdx.x == 0) g_rsum[e] = sm[0];
}
__global__ void lb2_kernel(float* __restrict__ dst) {
    float acc = 0.0f;
#pragma unroll
    for (int e = 0; e < 8; e++) { float m = g_rsum[e] * (1.0f / Tt); acc += m * m; }
    *dst = 8.0f * acc;
}

// ===========================================================================
// Launch
// ===========================================================================
extern "C" void kernel_launch(void* const* d_in, const int* in_sizes, int n_in,
                              void* d_out, int out_size) {
    const float* hs    = (const float*)d_in[0];
    const float* q_w   = (const float*)d_in[1];
    const float* q_b   = (const float*)d_in[2];
    const float* k_w   = (const float*)d_in[3];
    const float* k_b   = (const float*)d_in[4];
    const float* v_w   = (const float*)d_in[5];
    const float* v_b   = (const float*)d_in[6];
    const float* o_w   = (const float*)d_in[7];
    const float* o_b   = (const float*)d_in[8];
    const float* ln1_g = (const float*)d_in[9];
    const float* ln1_b = (const float*)d_in[10];
    const float* gatew = (const float*)d_in[11];
    const float* e_w1  = (const float*)d_in[12];
    const float* e_b1  = (const float*)d_in[13];
    const float* e_w2  = (const float*)d_in[14];
    const float* e_b2  = (const float*)d_in[15];
    const float* ln2_g = (const float*)d_in[16];
    const float* ln2_b = (const float*)d_in[17];
    float* out = (float*)d_out;

    (void)in_sizes; (void)n_in;

    cudaFuncSetAttribute(hgemm<0>, cudaFuncAttributeMaxDynamicSharedMemorySize, SMEM_B0);
    cudaFuncSetAttribute(hgemm<1>, cudaFuncAttributeMaxDynamicSharedMemorySize, SMEM_BS);
    cudaFuncSetAttribute(hgemm<2>, cudaFuncAttributeMaxDynamicSharedMemorySize, SMEM_BS);
    cudaFuncSetAttribute(hgemm<3>, cudaFuncAttributeMaxDynamicSharedMemorySize, SMEM_BS);

    __half* hsh = nullptr; cudaGetSymbolAddress((void**)&hsh, g_hsh);
    __half* atth= nullptr; cudaGetSymbolAddress((void**)&atth, g_atth);
    __half* h1h = nullptr; cudaGetSymbolAddress((void**)&h1h, g_h1h);
    __half* wqkv= nullptr; cudaGetSymbolAddress((void**)&wqkv, g_wqkvh);
    __half* woh = nullptr; cudaGetSymbolAddress((void**)&woh, g_woh);
    __half* w1h = nullptr; cudaGetSymbolAddress((void**)&w1h, g_w1h);
    __half* w2h = nullptr; cudaGetSymbolAddress((void**)&w2h, g_w2h);
    __half* hbh = nullptr; cudaGetSymbolAddress((void**)&hbh, g_hbufh);

    // 1) fused setup
    conv_all<<<(CONV_THREADS + 255) / 256, 256>>>(hs, q_w, k_w, v_w, o_w, e_w1, e_w2);

    // 2) merged QKV GEMM (fused RoPE/pack) -> flash attention
    hgemm<0><<<dim3(Tt/128, 3*Dd/128), 256, SMEM_B0>>>(hsh, wqkv, q_b, k_b, v_b);
    fattn<<<dim3(Ss/64, Bb*Hh), 128>>>();

    // 3) o-proj + LN1
    hgemm<3><<<dim3(Tt/128, Dd/64), 256, SMEM_BS>>>(atth, woh, o_b, nullptr, nullptr);
    add_ln<<<Tt, 128>>>(hs, ln1_g, ln1_b, nullptr, 0);

    // 4) router + lb loss
    router_kernel<<<Tt / 4, 128>>>(gatew);
    lb1_kernel<<<Ee, 256>>>();
    lb2_kernel<<<1, 1>>>(out + (out_size - 1));

    // 5) MoE FFN (gathered top-2) + final LN
    hgemm<1><<<dim3(Tt*2/128, FFNf/64, Ee), 256, SMEM_BS>>>(h1h, w1h, e_b1, nullptr, nullptr);
    hgemm<2><<<dim3(Tt*2/128, Dd/64, Ee), 256, SMEM_BS>>>(hbh, w2h, e_b2, nullptr, nullptr);

    add_ln<<<Tt, 128>>>(nullptr, ln2_g, ln2_b, out, 1);
}

// round 16
// speedup vs baseline: 1.0900x; 1.0900x over previous
#include <cuda_runtime.h>
#include <cuda_fp16.h>
#include <math.h>
#include <stdint.h>

// Problem constants
#define Bb   32
#define Ss   512
#define Dd   512
#define Hh   8
#define Ee   8
#define FFNf 2048
#define Tt   (Bb*Ss)     // 16384 tokens

// ===========================================================================
// Scratch (device globals)
// ===========================================================================
__device__ float g_h1[Tt*Dd];
__device__ float g_router[Tt*Ee];
__device__ int   g_cnt[Ee];
__device__ int   g_tok[Ee*Tt];
__device__ float g_wt[Ee*Tt];
__device__ float g_rsum[Ee];
__device__ float g_rsin[Ss*16];
__device__ float g_rcos[Ss*16];

// fp16 buffers
__device__ __half g_hsh  [Tt*Dd];
__device__ __half g_atth [Tt*Dd];
__device__ __half g_projh[Tt*Dd];
__device__ __half g_h1h  [Tt*Dd];
__device__ __half g_qh   [Tt*Dd];          // head-major [b][h][s][64]
__device__ __half g_kh   [Tt*Dd];
__device__ __half g_vh   [Tt*Dd];
__device__ __half g_wqkvh[3*Dd*Dd];        // q|k|v rows concatenated [1536][512]
__device__ __half g_woh  [Dd*Dd];
__device__ __half g_w1h  [(size_t)Ee*FFNf*Dd];
__device__ __half g_w2h  [(size_t)Ee*Dd*FFNf];
__device__ __half g_hbufh[(size_t)Tt*2*FFNf];
__device__ __half g_moe2h[(size_t)Tt*2*Dd];

// ===========================================================================
// One fused setup kernel: all fp32->fp16 conversions (segmented flat index),
// RoPE sin/cos table, expert counter zeroing.
// ===========================================================================
#define C_HS (Tt*Dd/4)
#define C_W  (Dd*Dd/4)
#define C_W1 (Ee*FFNf*Dd/4)
#define C_W2 (Ee*Dd*FFNf/4)
#define CONV_TOT (C_HS + 4*C_W + C_W1 + C_W2)
#define CONV_THREADS (CONV_TOT + Ss*16 + Ee)

__global__ void conv_all(const float* __restrict__ hs,
                         const float* __restrict__ qw, const float* __restrict__ kw,
                         const float* __restrict__ vw, const float* __restrict__ ow,
                         const float* __restrict__ w1, const float* __restrict__ w2) {
    int i = blockIdx.x * 256 + threadIdx.x;
    const int o1 = C_HS, o2 = o1 + C_W, o3 = o2 + C_W, o4 = o3 + C_W,
              o5 = o4 + C_W, o6 = o5 + C_W1, o7 = o6 + C_W2;
    if (i < o7) {
        const float* s; __half* d; int l;
        if (i < o1)      { s = hs; d = g_hsh;              l = i; }
        else if (i < o2) { s = qw; d = g_wqkvh;            l = i - o1; }
        else if (i < o3) { s = kw; d = g_wqkvh + Dd*Dd;    l = i - o2; }
        else if (i < o4) { s = vw; d = g_wqkvh + 2*Dd*Dd;  l = i - o3; }
        else if (i < o5) { s = ow; d = g_woh;              l = i - o4; }
        else if (i < o6) { s = w1; d = g_w1h;              l = i - o5; }
        else             { s = w2; d = g_w2h;              l = i - o6; }
        float4 v = ((const float4*)s)[l];
        ((__half2*)d)[2*l]     = __floats2half2_rn(v.x, v.y);
        ((__half2*)d)[2*l + 1] = __floats2half2_rn(v.z, v.w);
    } else if (i < o7 + Ss*16) {
        int idx = i - o7;
        int s = idx >> 4, ii = idx & 15;
        float inv = powf(10000.0f, -(float)ii / 16.0f);
        float ang = (float)s * inv;
        g_rsin[idx] = sinf(ang);
        g_rcos[idx] = cosf(ang);
    } else if (i < o7 + Ss*16 + Ee) {
        g_cnt[i - o7 - Ss*16] = 0;
    }
}

// ===========================================================================
// HMMA helpers
// ===========================================================================
__device__ __forceinline__ uint32_t smem_to_u32(const void* p) {
    uint32_t a;
    asm("{ .reg .u64 t; cvta.to.shared.u64 t, %1; cvt.u32.u64 %0, t; }" : "=r"(a) : "l"(p));
    return a;
}
__device__ __forceinline__ void ldsm_x4(uint32_t& r0, uint32_t& r1, uint32_t& r2, uint32_t& r3, uint32_t a) {
    asm volatile("ldmatrix.sync.aligned.m8n8.x4.shared.b16 {%0,%1,%2,%3}, [%4];"
        : "=r"(r0), "=r"(r1), "=r"(r2), "=r"(r3) : "r"(a));
}
__device__ __forceinline__ void ldsm_x2(uint32_t& r0, uint32_t& r1, uint32_t a) {
    asm volatile("ldmatrix.sync.aligned.m8n8.x2.shared.b16 {%0,%1}, [%2];"
        : "=r"(r0), "=r"(r1) : "r"(a));
}
__device__ __forceinline__ void ldsm_x2_trans(uint32_t& r0, uint32_t& r1, uint32_t a) {
    asm volatile("ldmatrix.sync.aligned.m8n8.x2.trans.shared.b16 {%0,%1}, [%2];"
        : "=r"(r0), "=r"(r1) : "r"(a));
}
__device__ __forceinline__ void mma16816(float* c, uint32_t a0, uint32_t a1, uint32_t a2, uint32_t a3,
                                         uint32_t b0, uint32_t b1) {
    asm volatile("mma.sync.aligned.m16n8k16.row.col.f32.f16.f16.f32 "
        "{%0,%1,%2,%3}, {%4,%5,%6,%7}, {%8,%9}, {%0,%1,%2,%3};"
        : "+f"(c[0]), "+f"(c[1]), "+f"(c[2]), "+f"(c[3])
        : "r"(a0), "r"(a1), "r"(a2), "r"(a3), "r"(b0), "r"(b1));
}
#define CP_ASYNC16(dst, src) \
    asm volatile("cp.async.cg.shared.global [%0], [%1], 16;" :: "r"(dst), "l"(src))
#define CP_COMMIT() asm volatile("cp.async.commit_group;" ::: "memory")
#define CP_WAIT0()  asm volatile("cp.async.wait_group 0;" ::: "memory")
#define CP_WAIT1()  asm volatile("cp.async.wait_group 1;" ::: "memory")

__device__ __forceinline__ uint32_t f2h2(float x, float y) {
    __half2 p = __floats2half2_rn(x, y);
    return *(uint32_t*)&p;
}

// ===========================================================================
// fp16 HMMA GEMM: 128x128 CTA tile, 8 warps, warp tile 64x32, k64 chunks,
// 3-stage cp.async pipeline, SW128 swizzle.  (round-14 record configuration:
// no trailing barrier — 3-buffer ring makes it dead.)
// MODE 0: merged QKV -> fp16 head-major q/k/v with fused RoPE + q-scale
// MODE 3: o-proj -> fp16 g_projh
// MODE 1: ffn1 gathered -> gelu fp16 g_hbufh
// MODE 2: ffn2 gathered -> wt*(.) fp16 g_moe2h
// ===========================================================================
#define SMEM_BYTES (2048 + 3*32768)

template<int MODE>
__global__ void __launch_bounds__(256) hgemm(const __half* __restrict__ A,
                                             const __half* __restrict__ Bw,
                                             const float* __restrict__ bp0,
                                             const float* __restrict__ bp1,
                                             const float* __restrict__ bp2) {
    constexpr int K  = (MODE == 2) ? FFNf : Dd;
    constexpr int NC = K / 64;
    constexpr int NW = (MODE == 0) ? 3*Dd : (MODE == 1) ? FFNf : Dd;
    constexpr bool GATH = (MODE == 1) || (MODE == 2);

    extern __shared__ char smem[];
    uint32_t sb = smem_to_u32(smem);
    int tid = threadIdx.x, wid = tid >> 5, lane = tid & 31;

    int e   = GATH ? blockIdx.z : 0;
    int cnt = GATH ? g_cnt[e] : Tt;
    int m0  = blockIdx.x * 128;
    if (m0 >= cnt) return;
    int n0  = blockIdx.y * 128;

    const __half* Wp = Bw + (size_t)e * NW * K;
    const float*  bp = bp0 + (size_t)e * NW;   // ffn bias base (MODE 1/2)

    int*   s_row  = (int*)(smem);
    int*   s_slot = (int*)(smem + 512);
    float* s_wt   = (float*)(smem + 1024);
    if (tid < 128) {
        int r = m0 + tid;
        if (!GATH) { s_row[tid] = r; s_slot[tid] = r; }
        else {
            if (r < cnt) {
                int sl = g_tok[e * Tt + r];
                s_slot[tid] = sl;
                s_row[tid]  = (MODE == 1) ? (sl >> 1) : sl;
                if (MODE == 2) s_wt[tid] = g_wt[e * Tt + r];
            } else { s_slot[tid] = -1; s_row[tid] = 0; if (MODE == 2) s_wt[tid] = 0.f; }
        }
    }
    __syncthreads();

    auto LOAD = [&](int c, int b) {
        int cbase = c * 64;
        uint32_t dstA = sb + 2048 + b * 32768;
        uint32_t dstB = dstA + 16384;
#pragma unroll
        for (int i = 0; i < 4; i++) {
            int u = tid + i * 256;
            int r = u >> 3, c16 = u & 7;
            uint32_t off = (uint32_t)(r * 128 + ((c16 * 16) ^ ((r & 7) << 4)));
            CP_ASYNC16(dstA + off, A + (size_t)s_row[r] * K + cbase + c16 * 8);
            CP_ASYNC16(dstB + off, Wp + (size_t)(n0 + r) * K + cbase + c16 * 8);
        }
        CP_COMMIT();
    };

    LOAD(0, 0);
    if (NC > 1) LOAD(1, 1);

    float acc[4][4][4];
#pragma unroll
    for (int a = 0; a < 4; a++)
#pragma unroll
        for (int b = 0; b < 4; b++)
#pragma unroll
            for (int c = 0; c < 4; c++) acc[a][b][c] = 0.f;

    int wm = (wid & 1) * 64, wn = (wid >> 1) * 32;
    uint32_t swz = (uint32_t)((lane & 7) << 4);
    int arow = wm + (lane & 7) + ((lane >> 3) & 1) * 8;
    uint32_t acolsel = ((lane >> 4) & 1) * 16;
    int brow = wn + (lane & 7);
    uint32_t bcolsel = ((lane >> 3) & 1) * 16;

    for (int c = 0; c < NC; c++) {
        if (c + 2 < NC) { CP_WAIT1(); } else { CP_WAIT0(); }
        __syncthreads();
        int buf = c % 3;
        uint32_t sA = sb + 2048 + buf * 32768;
        uint32_t sB = sA + 16384;
#pragma unroll
        for (int kk = 0; kk < 4; kk++) {
            uint32_t kb = (uint32_t)(kk * 32);
            uint32_t b0[4], b1[4];
#pragma unroll
            for (int nt = 0; nt < 4; nt++)
                ldsm_x2(b0[nt], b1[nt], sB + (brow + nt * 8) * 128 + ((kb + bcolsel) ^ swz));
#pragma unroll
            for (int mt = 0; mt < 4; mt++) {
                uint32_t a0, a1, a2, a3;
                ldsm_x4(a0, a1, a2, a3, sA + (arow + mt * 16) * 128 + ((kb + acolsel) ^ swz));
#pragma unroll
                for (int nt = 0; nt < 4; nt++)
                    mma16816(acc[mt][nt], a0, a1, a2, a3, b0[nt], b1[nt]);
            }
        }
        // no trailing barrier — LOAD(c+2) targets ring buffer (c+2)%3,
        // disjoint from buffers read by chunks c and c+1; the top-of-loop
        // __syncthreads bounds warp skew to one chunk.
        if (c + 2 < NC) LOAD(c + 2, (c + 2) % 3);
    }

    // ---- epilogue from registers ----
    int t4 = lane >> 2, tq = lane & 3;
#pragma unroll
    for (int mt = 0; mt < 4; mt++) {
#pragma unroll
        for (int rr = 0; rr < 2; rr++) {
            int rl = wm + mt * 16 + t4 + rr * 8;
            int slot = s_slot[rl];
            if (slot < 0) continue;
            if (MODE == 0) {
                int b = slot >> 9, spos = slot & 511;
                int ncb = n0 + wn;
                int which = ncb >> 9;
                int colb = ncb & 511;
                int h = colb >> 6;
                int hd0 = colb & 63;
                const float* bb = (which == 0) ? bp0 : (which == 1) ? bp1 : bp2;
                __half* dstb = ((which == 0) ? g_qh : (which == 1) ? g_kh : g_vh)
                               + ((size_t)(b * Hh + h) * Ss + spos) * 64;
                float vx[4], vy[4];
#pragma unroll
                for (int nt = 0; nt < 4; nt++) {
                    int col = colb + nt * 8 + tq * 2;
                    vx[nt] = acc[mt][nt][rr * 2 + 0] + bb[col];
                    vy[nt] = acc[mt][nt][rr * 2 + 1] + bb[col + 1];
                }
                if (which < 2 && hd0 == 0) {
#pragma unroll
                    for (int nt = 0; nt < 2; nt++) {
                        int i = nt * 8 + tq * 2;
                        float sn0 = g_rsin[spos * 16 + i],     cs0 = g_rcos[spos * 16 + i];
                        float sn1 = g_rsin[spos * 16 + i + 1], cs1 = g_rcos[spos * 16 + i + 1];
                        float x1 = vx[nt], x2 = vx[nt + 2];
                        vx[nt]     = x1 * cs0 - x2 * sn0;
                        vx[nt + 2] = x2 * cs0 + x1 * sn0;
                        float y1 = vy[nt], y2 = vy[nt + 2];
                        vy[nt]     = y1 * cs1 - y2 * sn1;
                        vy[nt + 2] = y2 * cs1 + y1 * sn1;
                    }
                }
                float qs = (which == 0) ? 0.125f : 1.0f;
#pragma unroll
                for (int nt = 0; nt < 4; nt++) {
                    int d = hd0 + nt * 8 + tq * 2;
                    *(__half2*)(dstb + d) = __floats2half2_rn(vx[nt] * qs, vy[nt] * qs);
                }
            } else {
#pragma unroll
                for (int nt = 0; nt < 4; nt++) {
                    int gc = n0 + wn + nt * 8 + tq * 2;
                    float c0 = acc[mt][nt][rr * 2 + 0];
                    float c1 = acc[mt][nt][rr * 2 + 1];
                    if (MODE == 3) {
                        *(__half2*)(g_projh + (size_t)slot * Dd + gc) =
                            __floats2half2_rn(c0 + bp0[gc], c1 + bp0[gc + 1]);
                    } else if (MODE == 1) {
                        float x0 = c0 + bp[gc], x1 = c1 + bp[gc + 1];
                        float g0 = 0.5f * x0 * (1.0f + erff(x0 * 0.70710678f));
                        float g1 = 0.5f * x1 * (1.0f + erff(x1 * 0.70710678f));
                        *(__half2*)(g_hbufh + (size_t)slot * FFNf + gc) = __floats2half2_rn(g0, g1);
                    } else {
                        float wt = s_wt[rl];
                        *(__half2*)(g_moe2h + (size_t)slot * Dd + gc) =
                            __floats2half2_rn(wt * (c0 + bp[gc]), wt * (c1 + bp[gc + 1]));
                    }
                }
            }
        }
    }
}

// ===========================================================================
// HMMA flash attention (round-8 form)
// ===========================================================================
__global__ void __launch_bounds__(128) fattn() {
    __shared__ __align__(16) __half Qs[64*64];
    __shared__ __align__(16) __half Ks[2][64*64];
    __shared__ __align__(16) __half Vs[2][64*64];

    int qt = blockIdx.x;
    int bh = blockIdx.y;
    int tid = threadIdx.x, wid = tid >> 5, lane = tid & 31;

    const __half* Qg = g_qh + ((size_t)bh * Ss + qt * 64) * 64;
    const __half* Kg = g_kh + (size_t)bh * Ss * 64;
    const __half* Vg = g_vh + (size_t)bh * Ss * 64;

    uint32_t sq  = smem_to_u32(Qs);
    uint32_t sk0 = smem_to_u32(Ks);
    uint32_t sv0 = smem_to_u32(Vs);

#pragma unroll
    for (int i = 0; i < 4; i++) {
        int u = tid + i * 128;
        int r = u >> 3, c16 = u & 7;
        uint32_t off = (uint32_t)(r * 128 + ((c16 * 16) ^ ((r & 7) << 4)));
        CP_ASYNC16(sq + off, Qg + r * 64 + c16 * 8);
    }
    CP_COMMIT();

    auto LOADKV = [&](int j, int b) {
        const __half* kg = Kg + j * 64 * 64;
        const __half* vg = Vg + j * 64 * 64;
        uint32_t dk = sk0 + b * 8192, dv = sv0 + b * 8192;
#pragma unroll
        for (int i = 0; i < 4; i++) {
            int u = tid + i * 128;
            int r = u >> 3, c16 = u & 7;
            uint32_t off = (uint32_t)(r * 128 + ((c16 * 16) ^ ((r & 7) << 4)));
            CP_ASYNC16(dk + off, kg + r * 64 + c16 * 8);
            CP_ASYNC16(dv + off, vg + r * 64 + c16 * 8);
        }
        CP_COMMIT();
    };
    LOADKV(0, 0);
    CP_WAIT0();
    __syncthreads();

    int wm = wid * 16;
    uint32_t swz = (uint32_t)((lane & 7) << 4);
    int arow = wm + (lane & 7) + ((lane >> 3) & 1) * 8;
    uint32_t acolsel = ((lane >> 4) & 1) * 16;
    uint32_t qa[4][4];
#pragma unroll
    for (int kk = 0; kk < 4; kk++)
        ldsm_x4(qa[kk][0], qa[kk][1], qa[kk][2], qa[kk][3],
                sq + arow * 128 + ((kk * 32 + acolsel) ^ swz));

    float o_acc[8][4];
#pragma unroll
    for (int a = 0; a < 8; a++)
#pragma unroll
        for (int b = 0; b < 4; b++) o_acc[a][b] = 0.f;
    float m0 = -1e30f, m1 = -1e30f, l0 = 0.f, l1 = 0.f;

    int brow = lane & 7;
    uint32_t bcolsel = ((lane >> 3) & 1) * 16;
    int vrow_l = lane & 15;

    for (int j = 0; j < 8; j++) {
        if (j + 1 < 8) LOADKV(j + 1, (j + 1) & 1);
        uint32_t sk = sk0 + (j & 1) * 8192;
        uint32_t sv = sv0 + (j & 1) * 8192;

        float s[8][4];
#pragma unroll
        for (int a = 0; a < 8; a++)
#pragma unroll
            for (int b = 0; b < 4; b++) s[a][b] = 0.f;
#pragma unroll
        for (int kk = 0; kk < 4; kk++) {
            uint32_t kb = (uint32_t)(kk * 32);
#pragma unroll
            for (int nt = 0; nt < 8; nt++) {
                uint32_t b0, b1;
                ldsm_x2(b0, b1, sk + (nt * 8 + brow) * 128 + ((kb + bcolsel) ^ swz));
                mma16816(s[nt], qa[kk][0], qa[kk][1], qa[kk][2], qa[kk][3], b0, b1);
            }
        }

        float tm0 = -1e30f, tm1 = -1e30f;
#pragma unroll
        for (int nt = 0; nt < 8; nt++) {
            tm0 = fmaxf(tm0, fmaxf(s[nt][0], s[nt][1]));
            tm1 = fmaxf(tm1, fmaxf(s[nt][2], s[nt][3]));
        }
        tm0 = fmaxf(tm0, __shfl_xor_sync(0xffffffffu, tm0, 1));
        tm0 = fmaxf(tm0, __shfl_xor_sync(0xffffffffu, tm0, 2));
        tm1 = fmaxf(tm1, __shfl_xor_sync(0xffffffffu, tm1, 1));
        tm1 = fmaxf(tm1, __shfl_xor_sync(0xffffffffu, tm1, 2));
        float nm0 = fmaxf(m0, tm0), nm1 = fmaxf(m1, tm1);
        float sc0 = __expf(m0 - nm0), sc1 = __expf(m1 - nm1);
        m0 = nm0; m1 = nm1;
        l0 *= sc0; l1 *= sc1;
#pragma unroll
        for (int nt = 0; nt < 8; nt++) {
            o_acc[nt][0] *= sc0; o_acc[nt][1] *= sc0;
            o_acc[nt][2] *= sc1; o_acc[nt][3] *= sc1;
        }
        float sum0 = 0.f, sum1 = 0.f;
#pragma unroll
        for (int nt = 0; nt < 8; nt++) {
            s[nt][0] = __expf(s[nt][0] - m0); s[nt][1] = __expf(s[nt][1] - m0);
            s[nt][2] = __expf(s[nt][2] - m1); s[nt][3] = __expf(s[nt][3] - m1);
            sum0 += s[nt][0] + s[nt][1];
            sum1 += s[nt][2] + s[nt][3];
        }
        sum0 += __shfl_xor_sync(0xffffffffu, sum0, 1);
        sum0 += __shfl_xor_sync(0xffffffffu, sum0, 2);
        sum1 += __shfl_xor_sync(0xffffffffu, sum1, 1);
        sum1 += __shfl_xor_sync(0xffffffffu, sum1, 2);
        l0 += sum0; l1 += sum1;

#pragma unroll
        for (int c = 0; c < 4; c++) {
            uint32_t a0 = f2h2(s[2*c][0],   s[2*c][1]);
            uint32_t a1 = f2h2(s[2*c][2],   s[2*c][3]);
            uint32_t a2 = f2h2(s[2*c+1][0], s[2*c+1][1]);
            uint32_t a3 = f2h2(s[2*c+1][2], s[2*c+1][3]);
            uint32_t vbase = sv + (16 * c + vrow_l) * 128;
#pragma unroll
            for (int nt = 0; nt < 8; nt++) {
                uint32_t b0, b1;
                ldsm_x2_trans(b0, b1, vbase + ((nt * 16) ^ swz));
                mma16816(o_acc[nt], a0, a1, a2, a3, b0, b1);
            }
        }

        CP_WAIT0();
        __syncthreads();
    }

    float inv0 = 1.0f / l0, inv1 = 1.0f / l1;
    int h = bh & 7, b = bh >> 3;
    int r0 = qt * 64 + wm + (lane >> 2);
    int t0 = b * Ss + r0;
#pragma unroll
    for (int nt = 0; nt < 8; nt++) {
        int col = h * 64 + nt * 8 + (lane & 3) * 2;
        *(__half2*)(g_atth + (size_t)t0 * Dd + col) =
            __floats2half2_rn(o_acc[nt][0] * inv0, o_acc[nt][1] * inv0);
        *(__half2*)(g_atth + (size_t)(t0 + 8) * Dd + col) =
            __floats2half2_rn(o_acc[nt][2] * inv1, o_acc[nt][3] * inv1);
    }
}

// ===========================================================================
// Residual + LayerNorm; mode 0 also emits fp16 h1.
// ===========================================================================
__global__ void add_ln(const float* __restrict__ xe,
                       const float* __restrict__ g, const float* __restrict__ bb,
                       float* __restrict__ oe, int mode) {
    int row = blockIdx.x, tid = threadIdx.x;
    size_t base = (size_t)row * Dd;
    float v[4]; float s = 0.0f, sq = 0.0f;
#pragma unroll
    for (int i = 0; i < 4; i++) {
        int c = tid + i * 128;
        float t;
        if (mode == 0) t = xe[base + c] + __half2float(g_projh[base + c]);
        else           t = g_h1[base + c]
                         + (__half2float(g_moe2h[(size_t)(2*row) * Dd + c])
                          + __half2float(g_moe2h[(size_t)(2*row+1) * Dd + c]));
        v[i] = t; s += t; sq += t * t;
    }
#pragma unroll
    for (int off = 16; off; off >>= 1) {
        s  += __shfl_down_sync(0xffffffffu, s,  off);
        sq += __shfl_down_sync(0xffffffffu, sq, off);
    }
    __shared__ float rs[4], rq[4];
    int warp = tid >> 5, lane = tid & 31;
    if (lane == 0) { rs[warp] = s; rq[warp] = sq; }
    __syncthreads();
    if (tid == 0) {
        float S = rs[0] + rs[1] + rs[2] + rs[3];
        float Q = rq[0] + rq[1] + rq[2] + rq[3];
        rs[0] = S; rq[0] = Q;
    }
    __syncthreads();
    float mean = rs[0] * (1.0f / Dd);
    float var  = rq[0] * (1.0f / Dd) - mean * mean;
    float rstd = rsqrtf(var + 1e-5f);
    float* o = (mode == 0) ? g_h1 : oe;
#pragma unroll
    for (int i = 0; i < 4; i++) {
        int c = tid + i * 128;
        float r = (v[i] - mean) * rstd * g[c] + bb[c];
        o[base + c] = r;
        if (mode == 0) g_h1h[base + c] = __float2half(r);
    }
}

// ===========================================================================
// Router + lb loss
// ===========================================================================
__global__ void router_kernel(const float* __restrict__ gw) {
    int warp = threadIdx.x >> 5, lane = threadIdx.x & 31;
    int t = blockIdx.x * 4 + warp;
    const float* x = g_h1 + (size_t)t * Dd;
    float acc[8] = {};
    for (int d = lane; d < Dd; d += 32) {
        float xv = x[d];
#pragma unroll
        for (int e = 0; e < 8; e++) acc[e] += xv * gw[e * Dd + d];
    }
#pragma unroll
    for (int e = 0; e < 8; e++)
#pragma unroll
        for (int off = 16; off; off >>= 1)
            acc[e] += __shfl_xor_sync(0xffffffffu, acc[e], off);

    if (lane == 0) {
        float mx = acc[0];
#pragma unroll
        for (int e = 1; e < 8; e++) mx = fmaxf(mx, acc[e]);
        float p[8], sm = 0.0f;
#pragma unroll
        for (int e = 0; e < 8; e++) { p[e] = __expf(acc[e] - mx); sm += p[e]; }
        float inv = 1.0f / sm;
#pragma unroll
        for (int e = 0; e < 8; e++) { p[e] *= inv; g_router[t * 8 + e] = p[e]; }
        int i1 = 0;
#pragma unroll
        for (int e = 1; e < 8; e++) if (p[e] > p[i1]) i1 = e;
        int i2 = (i1 == 0) ? 1 : 0;
#pragma unroll
        for (int e = 0; e < 8; e++) if (e != i1 && p[e] > p[i2]) i2 = e;
        float wsum = p[i1] + p[i2];
        int s1 = atomicAdd(&g_cnt[i1], 1);
        g_tok[i1 * Tt + s1] = t * 2;     g_wt[i1 * Tt + s1] = p[i1] / wsum;
        int s2 = atomicAdd(&g_cnt[i2], 1);
        g_tok[i2 * Tt + s2] = t * 2 + 1; g_wt[i2 * Tt + s2] = p[i2] / wsum;
    }
}

__global__ void lb1_kernel() {
    int e = blockIdx.x;
    float p = 0.0f;
    for (int t = threadIdx.x; t < Tt; t += 256) p += g_router[t * 8 + e];
    __shared__ float sm[256];
    sm[threadIdx.x] = p; __syncthreads();
    for (int s = 128; s; s >>= 1) {
        if (threadIdx.x < s) sm[threadIdx.x] += sm[threadIdx.x + s];
        __syncthreads();
    }
    if (threadIdx.x == 0) g_rsum[e] = sm[0];
}
__global__ void lb2_kernel(float* __restrict__ dst) {
    float acc = 0.0f;
#pragma unroll
    for (int e = 0; e < 8; e++) { float m = g_rsum[e] * (1.0f / Tt); acc += m * m; }
    *dst = 8.0f * acc;
}

// ===========================================================================
// Launch
// ===========================================================================
extern "C" void kernel_launch(void* const* d_in, const int* in_sizes, int n_in,
                              void* d_out, int out_size) {
    const float* hs    = (const float*)d_in[0];
    const float* q_w   = (const float*)d_in[1];
    const float* q_b   = (const float*)d_in[2];
    const float* k_w   = (const float*)d_in[3];
    const float* k_b   = (const float*)d_in[4];
    const float* v_w   = (const float*)d_in[5];
    const float* v_b   = (const float*)d_in[6];
    const float* o_w   = (const float*)d_in[7];
    const float* o_b   = (const float*)d_in[8];
    const float* ln1_g = (const float*)d_in[9];
    const float* ln1_b = (const float*)d_in[10];
    const float* gatew = (const float*)d_in[11];
    const float* e_w1  = (const float*)d_in[12];
    const float* e_b1  = (const float*)d_in[13];
    const float* e_w2  = (const float*)d_in[14];
    const float* e_b2  = (const float*)d_in[15];
    const float* ln2_g = (const float*)d_in[16];
    const float* ln2_b = (const float*)d_in[17];
    float* out = (float*)d_out;

    (void)in_sizes; (void)n_in;

    cudaFuncSetAttribute(hgemm<0>, cudaFuncAttributeMaxDynamicSharedMemorySize, SMEM_BYTES);
    cudaFuncSetAttribute(hgemm<1>, cudaFuncAttributeMaxDynamicSharedMemorySize, SMEM_BYTES);
    cudaFuncSetAttribute(hgemm<2>, cudaFuncAttributeMaxDynamicSharedMemorySize, SMEM_BYTES);
    cudaFuncSetAttribute(hgemm<3>, cudaFuncAttributeMaxDynamicSharedMemorySize, SMEM_BYTES);

    __half* hsh = nullptr; cudaGetSymbolAddress((void**)&hsh, g_hsh);
    __half* atth= nullptr; cudaGetSymbolAddress((void**)&atth, g_atth);
    __half* h1h = nullptr; cudaGetSymbolAddress((void**)&h1h, g_h1h);
    __half* wqkv= nullptr; cudaGetSymbolAddress((void**)&wqkv, g_wqkvh);
    __half* woh = nullptr; cudaGetSymbolAddress((void**)&woh, g_woh);
    __half* w1h = nullptr; cudaGetSymbolAddress((void**)&w1h, g_w1h);
    __half* w2h = nullptr; cudaGetSymbolAddress((void**)&w2h, g_w2h);
    __half* hbh = nullptr; cudaGetSymbolAddress((void**)&hbh, g_hbufh);

    // 1) fused setup: all conversions + rope table + counter zeroing
    conv_all<<<(CONV_THREADS + 255) / 256, 256>>>(hs, q_w, k_w, v_w, o_w, e_w1, e_w2);

    // 2) merged QKV GEMM (fused RoPE/pack) -> flash attention
    hgemm<0><<<dim3(Tt/128, 3*Dd/128), 256, SMEM_BYTES>>>(hsh, wqkv, q_b, k_b, v_b);
    fattn<<<dim3(Ss/64, Bb*Hh), 128>>>();

    // 3) o-proj + LN1
    hgemm<3><<<dim3(Tt/128, Dd/128), 256, SMEM_BYTES>>>(atth, woh, o_b, nullptr, nullptr);
    add_ln<<<Tt, 128>>>(hs, ln1_g, ln1_b, nullptr, 0);

    // 4) router + lb loss
    router_kernel<<<Tt / 4, 128>>>(gatew);
    lb1_kernel<<<Ee, 256>>>();
    lb2_kernel<<<1, 1>>>(out + (out_size - 1));

    // 5) MoE FFN (gathered top-2) + final LN
    hgemm<1><<<dim3(Tt*2/128, FFNf/128, Ee), 256, SMEM_BYTES>>>(h1h, w1h, e_b1, nullptr, nullptr);
    hgemm<2><<<dim3(Tt*2/128, Dd/128, Ee), 256, SMEM_BYTES>>>(hbh, w2h, e_b2, nullptr, nullptr);

    add_ln<<<Tt, 128>>>(nullptr, ln2_g, ln2_b, out, 1);
}

// round 17
// speedup vs baseline: 1.0971x; 1.0065x over previous
#include <cuda_runtime.h>
#include <cuda_fp16.h>
#include <math.h>
#include <stdint.h>

// Problem constants
#define Bb   32
#define Ss   512
#define Dd   512
#define Hh   8
#define Ee   8
#define FFNf 2048
#define Tt   (Bb*Ss)     // 16384 tokens

// ===========================================================================
// Scratch (device globals)
// ===========================================================================
__device__ float g_h1[Tt*Dd];
__device__ float g_router[Tt*Ee];
__device__ int   g_cnt[Ee];
__device__ int   g_tok[Ee*Tt];
__device__ float g_wt[Ee*Tt];
__device__ float g_rsum[Ee];
__device__ float g_rsin[Ss*16];
__device__ float g_rcos[Ss*16];

// fp16 buffers
__device__ __half g_hsh  [Tt*Dd];
__device__ __half g_atth [Tt*Dd];
__device__ __half g_projh[Tt*Dd];
__device__ __half g_h1h  [Tt*Dd];
__device__ __half g_qh   [Tt*Dd];          // head-major [b][h][s][64]
__device__ __half g_kh   [Tt*Dd];
__device__ __half g_vh   [Tt*Dd];
__device__ __half g_wqkvh[3*Dd*Dd];        // q|k|v rows concatenated [1536][512]
__device__ __half g_woh  [Dd*Dd];
__device__ __half g_w1h  [(size_t)Ee*FFNf*Dd];
__device__ __half g_w2h  [(size_t)Ee*Dd*FFNf];
__device__ __half g_hbufh[(size_t)Tt*2*FFNf];
__device__ __half g_moe2h[(size_t)Tt*2*Dd];

// ===========================================================================
// One fused setup kernel: all fp32->fp16 conversions (segmented flat index),
// RoPE sin/cos table, expert counter zeroing.
// ===========================================================================
#define C_HS (Tt*Dd/4)
#define C_W  (Dd*Dd/4)
#define C_W1 (Ee*FFNf*Dd/4)
#define C_W2 (Ee*Dd*FFNf/4)
#define CONV_TOT (C_HS + 4*C_W + C_W1 + C_W2)
#define CONV_THREADS (CONV_TOT + Ss*16 + Ee)

__global__ void conv_all(const float* __restrict__ hs,
                         const float* __restrict__ qw, const float* __restrict__ kw,
                         const float* __restrict__ vw, const float* __restrict__ ow,
                         const float* __restrict__ w1, const float* __restrict__ w2) {
    int i = blockIdx.x * 256 + threadIdx.x;
    const int o1 = C_HS, o2 = o1 + C_W, o3 = o2 + C_W, o4 = o3 + C_W,
              o5 = o4 + C_W, o6 = o5 + C_W1, o7 = o6 + C_W2;
    if (i < o7) {
        const float* s; __half* d; int l;
        if (i < o1)      { s = hs; d = g_hsh;              l = i; }
        else if (i < o2) { s = qw; d = g_wqkvh;            l = i - o1; }
        else if (i < o3) { s = kw; d = g_wqkvh + Dd*Dd;    l = i - o2; }
        else if (i < o4) { s = vw; d = g_wqkvh + 2*Dd*Dd;  l = i - o3; }
        else if (i < o5) { s = ow; d = g_woh;              l = i - o4; }
        else if (i < o6) { s = w1; d = g_w1h;              l = i - o5; }
        else             { s = w2; d = g_w2h;              l = i - o6; }
        float4 v = ((const float4*)s)[l];
        ((__half2*)d)[2*l]     = __floats2half2_rn(v.x, v.y);
        ((__half2*)d)[2*l + 1] = __floats2half2_rn(v.z, v.w);
    } else if (i < o7 + Ss*16) {
        int idx = i - o7;
        int s = idx >> 4, ii = idx & 15;
        float inv = powf(10000.0f, -(float)ii / 16.0f);
        float ang = (float)s * inv;
        g_rsin[idx] = sinf(ang);
        g_rcos[idx] = cosf(ang);
    } else if (i < o7 + Ss*16 + Ee) {
        g_cnt[i - o7 - Ss*16] = 0;
    }
}

// ===========================================================================
// HMMA helpers
// ===========================================================================
__device__ __forceinline__ uint32_t smem_to_u32(const void* p) {
    uint32_t a;
    asm("{ .reg .u64 t; cvta.to.shared.u64 t, %1; cvt.u32.u64 %0, t; }" : "=r"(a) : "l"(p));
    return a;
}
__device__ __forceinline__ void ldsm_x4(uint32_t& r0, uint32_t& r1, uint32_t& r2, uint32_t& r3, uint32_t a) {
    asm volatile("ldmatrix.sync.aligned.m8n8.x4.shared.b16 {%0,%1,%2,%3}, [%4];"
        : "=r"(r0), "=r"(r1), "=r"(r2), "=r"(r3) : "r"(a));
}
__device__ __forceinline__ void ldsm_x2(uint32_t& r0, uint32_t& r1, uint32_t a) {
    asm volatile("ldmatrix.sync.aligned.m8n8.x2.shared.b16 {%0,%1}, [%2];"
        : "=r"(r0), "=r"(r1) : "r"(a));
}
__device__ __forceinline__ void ldsm_x2_trans(uint32_t& r0, uint32_t& r1, uint32_t a) {
    asm volatile("ldmatrix.sync.aligned.m8n8.x2.trans.shared.b16 {%0,%1}, [%2];"
        : "=r"(r0), "=r"(r1) : "r"(a));
}
__device__ __forceinline__ void mma16816(float* c, uint32_t a0, uint32_t a1, uint32_t a2, uint32_t a3,
                                         uint32_t b0, uint32_t b1) {
    asm volatile("mma.sync.aligned.m16n8k16.row.col.f32.f16.f16.f32 "
        "{%0,%1,%2,%3}, {%4,%5,%6,%7}, {%8,%9}, {%0,%1,%2,%3};"
        : "+f"(c[0]), "+f"(c[1]), "+f"(c[2]), "+f"(c[3])
        : "r"(a0), "r"(a1), "r"(a2), "r"(a3), "r"(b0), "r"(b1));
}
#define CP_ASYNC16(dst, src) \
    asm volatile("cp.async.cg.shared.global [%0], [%1], 16;" :: "r"(dst), "l"(src))
#define CP_COMMIT() asm volatile("cp.async.commit_group;" ::: "memory")
#define CP_WAIT0()  asm volatile("cp.async.wait_group 0;" ::: "memory")
#define CP_WAIT1()  asm volatile("cp.async.wait_group 1;" ::: "memory")

__device__ __forceinline__ uint32_t f2h2(float x, float y) {
    __half2 p = __floats2half2_rn(x, y);
    return *(uint32_t*)&p;
}

// ===========================================================================
// fp16 HMMA GEMM: 128x128 CTA tile, 8 warps, warp tile 64x32, k64 chunks,
// 3-stage cp.async pipeline, SW128 swizzle.  (record configuration)
// MODE 0: merged QKV -> fp16 head-major q/k/v with fused RoPE + q-scale
// MODE 3: o-proj -> fp16 g_projh
// MODE 1: ffn1 gathered -> gelu fp16 g_hbufh
// MODE 2: ffn2 gathered -> wt*(.) fp16 g_moe2h
// ===========================================================================
#define SMEM_BYTES (2048 + 3*32768)

template<int MODE>
__global__ void __launch_bounds__(256) hgemm(const __half* __restrict__ A,
                                             const __half* __restrict__ Bw,
                                             const float* __restrict__ bp0,
                                             const float* __restrict__ bp1,
                                             const float* __restrict__ bp2) {
    constexpr int K  = (MODE == 2) ? FFNf : Dd;
    constexpr int NC = K / 64;
    constexpr int NW = (MODE == 0) ? 3*Dd : (MODE == 1) ? FFNf : Dd;
    constexpr bool GATH = (MODE == 1) || (MODE == 2);

    extern __shared__ char smem[];
    uint32_t sb = smem_to_u32(smem);
    int tid = threadIdx.x, wid = tid >> 5, lane = tid & 31;

    int e   = GATH ? blockIdx.z : 0;
    int cnt = GATH ? g_cnt[e] : Tt;
    int m0  = blockIdx.x * 128;
    if (m0 >= cnt) return;
    int n0  = blockIdx.y * 128;

    const __half* Wp = Bw + (size_t)e * NW * K;
    const float*  bp = bp0 + (size_t)e * NW;   // ffn bias base (MODE 1/2)

    int*   s_row  = (int*)(smem);
    int*   s_slot = (int*)(smem + 512);
    float* s_wt   = (float*)(smem + 1024);
    if (tid < 128) {
        int r = m0 + tid;
        if (!GATH) { s_row[tid] = r; s_slot[tid] = r; }
        else {
            if (r < cnt) {
                int sl = g_tok[e * Tt + r];
                s_slot[tid] = sl;
                s_row[tid]  = (MODE == 1) ? (sl >> 1) : sl;
                if (MODE == 2) s_wt[tid] = g_wt[e * Tt + r];
            } else { s_slot[tid] = -1; s_row[tid] = 0; if (MODE == 2) s_wt[tid] = 0.f; }
        }
    }
    __syncthreads();

    auto LOAD = [&](int c, int b) {
        int cbase = c * 64;
        uint32_t dstA = sb + 2048 + b * 32768;
        uint32_t dstB = dstA + 16384;
#pragma unroll
        for (int i = 0; i < 4; i++) {
            int u = tid + i * 256;
            int r = u >> 3, c16 = u & 7;
            uint32_t off = (uint32_t)(r * 128 + ((c16 * 16) ^ ((r & 7) << 4)));
            CP_ASYNC16(dstA + off, A + (size_t)s_row[r] * K + cbase + c16 * 8);
            CP_ASYNC16(dstB + off, Wp + (size_t)(n0 + r) * K + cbase + c16 * 8);
        }
        CP_COMMIT();
    };

    LOAD(0, 0);
    if (NC > 1) LOAD(1, 1);

    float acc[4][4][4];
#pragma unroll
    for (int a = 0; a < 4; a++)
#pragma unroll
        for (int b = 0; b < 4; b++)
#pragma unroll
            for (int c = 0; c < 4; c++) acc[a][b][c] = 0.f;

    int wm = (wid & 1) * 64, wn = (wid >> 1) * 32;
    uint32_t swz = (uint32_t)((lane & 7) << 4);
    int arow = wm + (lane & 7) + ((lane >> 3) & 1) * 8;
    uint32_t acolsel = ((lane >> 4) & 1) * 16;
    int brow = wn + (lane & 7);
    uint32_t bcolsel = ((lane >> 3) & 1) * 16;

    for (int c = 0; c < NC; c++) {
        if (c + 2 < NC) { CP_WAIT1(); } else { CP_WAIT0(); }
        __syncthreads();
        int buf = c % 3;
        uint32_t sA = sb + 2048 + buf * 32768;
        uint32_t sB = sA + 16384;
#pragma unroll
        for (int kk = 0; kk < 4; kk++) {
            uint32_t kb = (uint32_t)(kk * 32);
            uint32_t b0[4], b1[4];
#pragma unroll
            for (int nt = 0; nt < 4; nt++)
                ldsm_x2(b0[nt], b1[nt], sB + (brow + nt * 8) * 128 + ((kb + bcolsel) ^ swz));
#pragma unroll
            for (int mt = 0; mt < 4; mt++) {
                uint32_t a0, a1, a2, a3;
                ldsm_x4(a0, a1, a2, a3, sA + (arow + mt * 16) * 128 + ((kb + acolsel) ^ swz));
#pragma unroll
                for (int nt = 0; nt < 4; nt++)
                    mma16816(acc[mt][nt], a0, a1, a2, a3, b0[nt], b1[nt]);
            }
        }
        // no trailing barrier — ring buffer (c+2)%3 is disjoint from c, c+1
        if (c + 2 < NC) LOAD(c + 2, (c + 2) % 3);
    }

    // ---- epilogue from registers ----
    int t4 = lane >> 2, tq = lane & 3;
#pragma unroll
    for (int mt = 0; mt < 4; mt++) {
#pragma unroll
        for (int rr = 0; rr < 2; rr++) {
            int rl = wm + mt * 16 + t4 + rr * 8;
            int slot = s_slot[rl];
            if (slot < 0) continue;
            if (MODE == 0) {
                int b = slot >> 9, spos = slot & 511;
                int ncb = n0 + wn;
                int which = ncb >> 9;
                int colb = ncb & 511;
                int h = colb >> 6;
                int hd0 = colb & 63;
                const float* bb = (which == 0) ? bp0 : (which == 1) ? bp1 : bp2;
                __half* dstb = ((which == 0) ? g_qh : (which == 1) ? g_kh : g_vh)
                               + ((size_t)(b * Hh + h) * Ss + spos) * 64;
                float vx[4], vy[4];
#pragma unroll
                for (int nt = 0; nt < 4; nt++) {
                    int col = colb + nt * 8 + tq * 2;
                    vx[nt] = acc[mt][nt][rr * 2 + 0] + bb[col];
                    vy[nt] = acc[mt][nt][rr * 2 + 1] + bb[col + 1];
                }
                if (which < 2 && hd0 == 0) {
#pragma unroll
                    for (int nt = 0; nt < 2; nt++) {
                        int i = nt * 8 + tq * 2;
                        float sn0 = g_rsin[spos * 16 + i],     cs0 = g_rcos[spos * 16 + i];
                        float sn1 = g_rsin[spos * 16 + i + 1], cs1 = g_rcos[spos * 16 + i + 1];
                        float x1 = vx[nt], x2 = vx[nt + 2];
                        vx[nt]     = x1 * cs0 - x2 * sn0;
                        vx[nt + 2] = x2 * cs0 + x1 * sn0;
                        float y1 = vy[nt], y2 = vy[nt + 2];
                        vy[nt]     = y1 * cs1 - y2 * sn1;
                        vy[nt + 2] = y2 * cs1 + y1 * sn1;
                    }
                }
                float qs = (which == 0) ? 0.125f : 1.0f;
#pragma unroll
                for (int nt = 0; nt < 4; nt++) {
                    int d = hd0 + nt * 8 + tq * 2;
                    *(__half2*)(dstb + d) = __floats2half2_rn(vx[nt] * qs, vy[nt] * qs);
                }
            } else {
#pragma unroll
                for (int nt = 0; nt < 4; nt++) {
                    int gc = n0 + wn + nt * 8 + tq * 2;
                    float c0 = acc[mt][nt][rr * 2 + 0];
                    float c1 = acc[mt][nt][rr * 2 + 1];
                    if (MODE == 3) {
                        *(__half2*)(g_projh + (size_t)slot * Dd + gc) =
                            __floats2half2_rn(c0 + bp0[gc], c1 + bp0[gc + 1]);
                    } else if (MODE == 1) {
                        float x0 = c0 + bp[gc], x1 = c1 + bp[gc + 1];
                        float g0 = 0.5f * x0 * (1.0f + erff(x0 * 0.70710678f));
                        float g1 = 0.5f * x1 * (1.0f + erff(x1 * 0.70710678f));
                        *(__half2*)(g_hbufh + (size_t)slot * FFNf + gc) = __floats2half2_rn(g0, g1);
                    } else {
                        float wt = s_wt[rl];
                        *(__half2*)(g_moe2h + (size_t)slot * Dd + gc) =
                            __floats2half2_rn(wt * (c0 + bp[gc]), wt * (c1 + bp[gc + 1]));
                    }
                }
            }
        }
    }
}

// ===========================================================================
// HMMA flash attention: q-tile 128 rows, 8 warps/256 threads.
// KV tiles (64 rows) double-buffered; each (b,h)'s KV now streamed 4x (was 8x).
// Per-warp math identical to the 64-row version (warp owns 16 q rows).
// ===========================================================================
__global__ void __launch_bounds__(256) fattn() {
    __shared__ __align__(16) __half Qs[128*64];     // 16 KB
    __shared__ __align__(16) __half Ks[2][64*64];   // 16 KB
    __shared__ __align__(16) __half Vs[2][64*64];   // 16 KB  (48 KB total)

    int qt = blockIdx.x;          // 0..3 (128-row q tiles)
    int bh = blockIdx.y;
    int tid = threadIdx.x, wid = tid >> 5, lane = tid & 31;

    const __half* Qg = g_qh + ((size_t)bh * Ss + qt * 128) * 64;
    const __half* Kg = g_kh + (size_t)bh * Ss * 64;
    const __half* Vg = g_vh + (size_t)bh * Ss * 64;

    uint32_t sq  = smem_to_u32(Qs);
    uint32_t sk0 = smem_to_u32(Ks);
    uint32_t sv0 = smem_to_u32(Vs);

    // Q tile: 128 rows x 128B = 1024 16B-chunks; 256 threads x 4
#pragma unroll
    for (int i = 0; i < 4; i++) {
        int u = tid + i * 256;
        int r = u >> 3, c16 = u & 7;
        uint32_t off = (uint32_t)(r * 128 + ((c16 * 16) ^ ((r & 7) << 4)));
        CP_ASYNC16(sq + off, Qg + r * 64 + c16 * 8);
    }
    CP_COMMIT();

    auto LOADKV = [&](int j, int b) {
        const __half* kg = Kg + j * 64 * 64;
        const __half* vg = Vg + j * 64 * 64;
        uint32_t dk = sk0 + b * 8192, dv = sv0 + b * 8192;
#pragma unroll
        for (int i = 0; i < 2; i++) {
            int u = tid + i * 256;
            int r = u >> 3, c16 = u & 7;
            uint32_t off = (uint32_t)(r * 128 + ((c16 * 16) ^ ((r & 7) << 4)));
            CP_ASYNC16(dk + off, kg + r * 64 + c16 * 8);
            CP_ASYNC16(dv + off, vg + r * 64 + c16 * 8);
        }
        CP_COMMIT();
    };
    LOADKV(0, 0);
    CP_WAIT0();
    __syncthreads();

    int wm = wid * 16;            // warp q-row base: 0..112
    uint32_t swz = (uint32_t)((lane & 7) << 4);
    int arow = wm + (lane & 7) + ((lane >> 3) & 1) * 8;
    uint32_t acolsel = ((lane >> 4) & 1) * 16;
    uint32_t qa[4][4];
#pragma unroll
    for (int kk = 0; kk < 4; kk++)
        ldsm_x4(qa[kk][0], qa[kk][1], qa[kk][2], qa[kk][3],
                sq + arow * 128 + ((kk * 32 + acolsel) ^ swz));

    float o_acc[8][4];
#pragma unroll
    for (int a = 0; a < 8; a++)
#pragma unroll
        for (int b = 0; b < 4; b++) o_acc[a][b] = 0.f;
    float m0 = -1e30f, m1 = -1e30f, l0 = 0.f, l1 = 0.f;

    int brow = lane & 7;
    uint32_t bcolsel = ((lane >> 3) & 1) * 16;
    int vrow_l = lane & 15;

    for (int j = 0; j < 8; j++) {
        if (j + 1 < 8) LOADKV(j + 1, (j + 1) & 1);
        uint32_t sk = sk0 + (j & 1) * 8192;
        uint32_t sv = sv0 + (j & 1) * 8192;

        float s[8][4];
#pragma unroll
        for (int a = 0; a < 8; a++)
#pragma unroll
            for (int b = 0; b < 4; b++) s[a][b] = 0.f;
#pragma unroll
        for (int kk = 0; kk < 4; kk++) {
            uint32_t kb = (uint32_t)(kk * 32);
#pragma unroll
            for (int nt = 0; nt < 8; nt++) {
                uint32_t b0, b1;
                ldsm_x2(b0, b1, sk + (nt * 8 + brow) * 128 + ((kb + bcolsel) ^ swz));
                mma16816(s[nt], qa[kk][0], qa[kk][1], qa[kk][2], qa[kk][3], b0, b1);
            }
        }

        float tm0 = -1e30f, tm1 = -1e30f;
#pragma unroll
        for (int nt = 0; nt < 8; nt++) {
            tm0 = fmaxf(tm0, fmaxf(s[nt][0], s[nt][1]));
            tm1 = fmaxf(tm1, fmaxf(s[nt][2], s[nt][3]));
        }
        tm0 = fmaxf(tm0, __shfl_xor_sync(0xffffffffu, tm0, 1));
        tm0 = fmaxf(tm0, __shfl_xor_sync(0xffffffffu, tm0, 2));
        tm1 = fmaxf(tm1, __shfl_xor_sync(0xffffffffu, tm1, 1));
        tm1 = fmaxf(tm1, __shfl_xor_sync(0xffffffffu, tm1, 2));
        float nm0 = fmaxf(m0, tm0), nm1 = fmaxf(m1, tm1);
        float sc0 = __expf(m0 - nm0), sc1 = __expf(m1 - nm1);
        m0 = nm0; m1 = nm1;
        l0 *= sc0; l1 *= sc1;
#pragma unroll
        for (int nt = 0; nt < 8; nt++) {
            o_acc[nt][0] *= sc0; o_acc[nt][1] *= sc0;
            o_acc[nt][2] *= sc1; o_acc[nt][3] *= sc1;
        }
        float sum0 = 0.f, sum1 = 0.f;
#pragma unroll
        for (int nt = 0; nt < 8; nt++) {
            s[nt][0] = __expf(s[nt][0] - m0); s[nt][1] = __expf(s[nt][1] - m0);
            s[nt][2] = __expf(s[nt][2] - m1); s[nt][3] = __expf(s[nt][3] - m1);
            sum0 += s[nt][0] + s[nt][1];
            sum1 += s[nt][2] + s[nt][3];
        }
        sum0 += __shfl_xor_sync(0xffffffffu, sum0, 1);
        sum0 += __shfl_xor_sync(0xffffffffu, sum0, 2);
        sum1 += __shfl_xor_sync(0xffffffffu, sum1, 1);
        sum1 += __shfl_xor_sync(0xffffffffu, sum1, 2);
        l0 += sum0; l1 += sum1;

#pragma unroll
        for (int c = 0; c < 4; c++) {
            uint32_t a0 = f2h2(s[2*c][0],   s[2*c][1]);
            uint32_t a1 = f2h2(s[2*c][2],   s[2*c][3]);
            uint32_t a2 = f2h2(s[2*c+1][0], s[2*c+1][1]);
            uint32_t a3 = f2h2(s[2*c+1][2], s[2*c+1][3]);
            uint32_t vbase = sv + (16 * c + vrow_l) * 128;
#pragma unroll
            for (int nt = 0; nt < 8; nt++) {
                uint32_t b0, b1;
                ldsm_x2_trans(b0, b1, vbase + ((nt * 16) ^ swz));
                mma16816(o_acc[nt], a0, a1, a2, a3, b0, b1);
            }
        }

        CP_WAIT0();
        __syncthreads();
    }

    float inv0 = 1.0f / l0, inv1 = 1.0f / l1;
    int h = bh & 7, b = bh >> 3;
    int r0 = qt * 128 + wm + (lane >> 2);
    int t0 = b * Ss + r0;
#pragma unroll
    for (int nt = 0; nt < 8; nt++) {
        int col = h * 64 + nt * 8 + (lane & 3) * 2;
        *(__half2*)(g_atth + (size_t)t0 * Dd + col) =
            __floats2half2_rn(o_acc[nt][0] * inv0, o_acc[nt][1] * inv0);
        *(__half2*)(g_atth + (size_t)(t0 + 8) * Dd + col) =
            __floats2half2_rn(o_acc[nt][2] * inv1, o_acc[nt][3] * inv1);
    }
}

// ===========================================================================
// Residual + LayerNorm; mode 0 also emits fp16 h1.
// ===========================================================================
__global__ void add_ln(const float* __restrict__ xe,
                       const float* __restrict__ g, const float* __restrict__ bb,
                       float* __restrict__ oe, int mode) {
    int row = blockIdx.x, tid = threadIdx.x;
    size_t base = (size_t)row * Dd;
    float v[4]; float s = 0.0f, sq = 0.0f;
#pragma unroll
    for (int i = 0; i < 4; i++) {
        int c = tid + i * 128;
        float t;
        if (mode == 0) t = xe[base + c] + __half2float(g_projh[base + c]);
        else           t = g_h1[base + c]
                         + (__half2float(g_moe2h[(size_t)(2*row) * Dd + c])
                          + __half2float(g_moe2h[(size_t)(2*row+1) * Dd + c]));
        v[i] = t; s += t; sq += t * t;
    }
#pragma unroll
    for (int off = 16; off; off >>= 1) {
        s  += __shfl_down_sync(0xffffffffu, s,  off);
        sq += __shfl_down_sync(0xffffffffu, sq, off);
    }
    __shared__ float rs[4], rq[4];
    int warp = tid >> 5, lane = tid & 31;
    if (lane == 0) { rs[warp] = s; rq[warp] = sq; }
    __syncthreads();
    if (tid == 0) {
        float S = rs[0] + rs[1] + rs[2] + rs[3];
        float Q = rq[0] + rq[1] + rq[2] + rq[3];
        rs[0] = S; rq[0] = Q;
    }
    __syncthreads();
    float mean = rs[0] * (1.0f / Dd);
    float var  = rq[0] * (1.0f / Dd) - mean * mean;
    float rstd = rsqrtf(var + 1e-5f);
    float* o = (mode == 0) ? g_h1 : oe;
#pragma unroll
    for (int i = 0; i < 4; i++) {
        int c = tid + i * 128;
        float r = (v[i] - mean) * rstd * g[c] + bb[c];
        o[base + c] = r;
        if (mode == 0) g_h1h[base + c] = __float2half(r);
    }
}

// ===========================================================================
// Router + lb loss
// ===========================================================================
__global__ void router_kernel(const float* __restrict__ gw) {
    int warp = threadIdx.x >> 5, lane = threadIdx.x & 31;
    int t = blockIdx.x * 4 + warp;
    const float* x = g_h1 + (size_t)t * Dd;
    float acc[8] = {};
    for (int d = lane; d < Dd; d += 32) {
        float xv = x[d];
#pragma unroll
        for (int e = 0; e < 8; e++) acc[e] += xv * gw[e * Dd + d];
    }
#pragma unroll
    for (int e = 0; e < 8; e++)
#pragma unroll
        for (int off = 16; off; off >>= 1)
            acc[e] += __shfl_xor_sync(0xffffffffu, acc[e], off);

    if (lane == 0) {
        float mx = acc[0];
#pragma unroll
        for (int e = 1; e < 8; e++) mx = fmaxf(mx, acc[e]);
        float p[8], sm = 0.0f;
#pragma unroll
        for (int e = 0; e < 8; e++) { p[e] = __expf(acc[e] - mx); sm += p[e]; }
        float inv = 1.0f / sm;
#pragma unroll
        for (int e = 0; e < 8; e++) { p[e] *= inv; g_router[t * 8 + e] = p[e]; }
        int i1 = 0;
#pragma unroll
        for (int e = 1; e < 8; e++) if (p[e] > p[i1]) i1 = e;
        int i2 = (i1 == 0) ? 1 : 0;
#pragma unroll
        for (int e = 0; e < 8; e++) if (e != i1 && p[e] > p[i2]) i2 = e;
        float wsum = p[i1] + p[i2];
        int s1 = atomicAdd(&g_cnt[i1], 1);
        g_tok[i1 * Tt + s1] = t * 2;     g_wt[i1 * Tt + s1] = p[i1] / wsum;
        int s2 = atomicAdd(&g_cnt[i2], 1);
        g_tok[i2 * Tt + s2] = t * 2 + 1; g_wt[i2 * Tt + s2] = p[i2] / wsum;
    }
}

__global__ void lb1_kernel() {
    int e = blockIdx.x;
    float p = 0.0f;
    for (int t = threadIdx.x; t < Tt; t += 256) p += g_router[t * 8 + e];
    __shared__ float sm[256];
    sm[threadIdx.x] = p; __syncthreads();
    for (int s = 128; s; s >>= 1) {
        if (threadIdx.x < s) sm[threadIdx.x] += sm[threadIdx.x + s];
        __syncthreads();
    }
    if (threadIdx.x == 0) g_rsum[e] = sm[0];
}
__global__ void lb2_kernel(float* __restrict__ dst) {
    float acc = 0.0f;
#pragma unroll
    for (int e = 0; e < 8; e++) { float m = g_rsum[e] * (1.0f / Tt); acc += m * m; }
    *dst = 8.0f * acc;
}

// ===========================================================================
// Launch
// ===========================================================================
extern "C" void kernel_launch(void* const* d_in, const int* in_sizes, int n_in,
                              void* d_out, int out_size) {
    const float* hs    = (const float*)d_in[0];
    const float* q_w   = (const float*)d_in[1];
    const float* q_b   = (const float*)d_in[2];
    const float* k_w   = (const float*)d_in[3];
    const float* k_b   = (const float*)d_in[4];
    const float* v_w   = (const float*)d_in[5];
    const float* v_b   = (const float*)d_in[6];
    const float* o_w   = (const float*)d_in[7];
    const float* o_b   = (const float*)d_in[8];
    const float* ln1_g = (const float*)d_in[9];
    const float* ln1_b = (const float*)d_in[10];
    const float* gatew = (const float*)d_in[11];
    const float* e_w1  = (const float*)d_in[12];
    const float* e_b1  = (const float*)d_in[13];
    const float* e_w2  = (const float*)d_in[14];
    const float* e_b2  = (const float*)d_in[15];
    const float* ln2_g = (const float*)d_in[16];
    const float* ln2_b = (const float*)d_in[17];
    float* out = (float*)d_out;

    (void)in_sizes; (void)n_in;

    cudaFuncSetAttribute(hgemm<0>, cudaFuncAttributeMaxDynamicSharedMemorySize, SMEM_BYTES);
    cudaFuncSetAttribute(hgemm<1>, cudaFuncAttributeMaxDynamicSharedMemorySize, SMEM_BYTES);
    cudaFuncSetAttribute(hgemm<2>, cudaFuncAttributeMaxDynamicSharedMemorySize, SMEM_BYTES);
    cudaFuncSetAttribute(hgemm<3>, cudaFuncAttributeMaxDynamicSharedMemorySize, SMEM_BYTES);

    __half* hsh = nullptr; cudaGetSymbolAddress((void**)&hsh, g_hsh);
    __half* atth= nullptr; cudaGetSymbolAddress((void**)&atth, g_atth);
    __half* h1h = nullptr; cudaGetSymbolAddress((void**)&h1h, g_h1h);
    __half* wqkv= nullptr; cudaGetSymbolAddress((void**)&wqkv, g_wqkvh);
    __half* woh = nullptr; cudaGetSymbolAddress((void**)&woh, g_woh);
    __half* w1h = nullptr; cudaGetSymbolAddress((void**)&w1h, g_w1h);
    __half* w2h = nullptr; cudaGetSymbolAddress((void**)&w2h, g_w2h);
    __half* hbh = nullptr; cudaGetSymbolAddress((void**)&hbh, g_hbufh);

    // 1) fused setup: all conversions + rope table + counter zeroing
    conv_all<<<(CONV_THREADS + 255) / 256, 256>>>(hs, q_w, k_w, v_w, o_w, e_w1, e_w2);

    // 2) merged QKV GEMM (fused RoPE/pack) -> flash attention (128-row q-tiles)
    hgemm<0><<<dim3(Tt/128, 3*Dd/128), 256, SMEM_BYTES>>>(hsh, wqkv, q_b, k_b, v_b);
    fattn<<<dim3(Ss/128, Bb*Hh), 256>>>();

    // 3) o-proj + LN1
    hgemm<3><<<dim3(Tt/128, Dd/128), 256, SMEM_BYTES>>>(atth, woh, o_b, nullptr, nullptr);
    add_ln<<<Tt, 128>>>(hs, ln1_g, ln1_b, nullptr, 0);

    // 4) router + lb loss
    router_kernel<<<Tt / 4, 128>>>(gatew);
    lb1_kernel<<<Ee, 256>>>();
    lb2_kernel<<<1, 1>>>(out + (out_size - 1));

    // 5) MoE FFN (gathered top-2) + final LN
    hgemm<1><<<dim3(Tt*2/128, FFNf/128, Ee), 256, SMEM_BYTES>>>(h1h, w1h, e_b1, nullptr, nullptr);
    hgemm<2><<<dim3(Tt*2/128, Dd/128, Ee), 256, SMEM_BYTES>>>(hbh, w2h, e_b2, nullptr, nullptr);

    add_ln<<<Tt, 128>>>(nullptr, ln2_g, ln2_b, out, 1);
}